// round 5
// baseline (speedup 1.0000x reference)
#include <cuda_runtime.h>
#include <math.h>

#define T_STEPS   64
#define NCH       4              // chunks of 16 timesteps
#define THREADS   256
#define MAXBLOCKS 4096

// Deterministic per-block log-likelihood partials + self-resetting ticket.
__device__ double       g_part[MAXBLOCKS];
__device__ unsigned int g_ticket;   // zero-init; last block resets to 0

__global__ __launch_bounds__(THREADS, 4)
void hmm_filter_kernel(
    const float* __restrict__ G,   // (N,1)
    const float* __restrict__ S,   // (N,T)
    const float* __restrict__ C,   // (N,T)
    const float* __restrict__ Y,   // (N,T)
    const float* __restrict__ L,   // (N,3)
    const float* __restrict__ p_psi,
    const float* __restrict__ p_gS,
    const float* __restrict__ p_gC,
    const float* __restrict__ p_gG,
    const float* __restrict__ p_gGS,
    const float* __restrict__ p_gGC,
    const float* __restrict__ p_gLw,   // (1,3)
    const float* __restrict__ p_lsz,
    const float* __restrict__ p_b0,
    const float* __restrict__ p_bZ,
    const float* __restrict__ p_bS,
    const float* __restrict__ p_bG,
    const float* __restrict__ p_bGS,
    const float* __restrict__ p_bLw,   // (1,3)
    float* __restrict__ Zf,            // (N,T)
    float* __restrict__ Zv,            // (N,T)
    float* __restrict__ out_ll,
    int N)
{
    __shared__ float  wsum[THREADS / 32];
    __shared__ double dsum[THREADS / 32];
    __shared__ bool   is_last;

    // ---- scalar params ----
    const float psi  = __ldg(p_psi);
    const float gS   = __ldg(p_gS);
    const float gC   = __ldg(p_gC);
    const float gG   = __ldg(p_gG);
    const float gGS  = __ldg(p_gGS);
    const float gGC  = __ldg(p_gGC);
    const float lsz  = __ldg(p_lsz);
    const float b0   = __ldg(p_b0);
    const float bZ   = __ldg(p_bZ);
    const float bS   = __ldg(p_bS);
    const float bG   = __ldg(p_bG);
    const float bGS  = __ldg(p_bGS);
    const float gw0  = __ldg(p_gLw + 0), gw1 = __ldg(p_gLw + 1), gw2 = __ldg(p_gLw + 2);
    const float bw0  = __ldg(p_bLw + 0), bw1 = __ldg(p_bLw + 1), bw2 = __ldg(p_bLw + 2);

    const float sz     = expf(lsz);
    const float sigma2 = sz * sz;
    const float psi2   = psi * psi;
    const float bZ2    = bZ * bZ;

    const int tid  = threadIdx.x;
    const int lane = tid & 31;
    const int wid  = tid >> 5;
    const int row  = blockIdx.x * THREADS + tid;
    const bool valid = (row < N);

    // Per-row fused constants
    float tc0 = 0.f, tS = 0.f, tC = 0.f, ob0 = 0.f, oS = 0.f;
    if (valid) {
        const float Gn = __ldg(G + row);
        const float l0 = __ldg(L + 3 * (size_t)row + 0);
        const float l1 = __ldg(L + 3 * (size_t)row + 1);
        const float l2 = __ldg(L + 3 * (size_t)row + 2);
        const float gL = fmaf(gw0, l0, fmaf(gw1, l1, gw2 * l2));
        const float bL = fmaf(bw0, l0, fmaf(bw1, l1, bw2 * l2));
        tc0 = fmaf(gG, Gn, gL);
        tS  = fmaf(gGS, Gn, gS);
        tC  = fmaf(gGC, Gn, gC);
        ob0 = fmaf(bG, Gn, b0) + bL;
        oS  = fmaf(bGS, Gn, bS);
    }

    const float4* __restrict__ S4  = reinterpret_cast<const float4*>(S);
    const float4* __restrict__ C4  = reinterpret_cast<const float4*>(C);
    const float4* __restrict__ Y4  = reinterpret_cast<const float4*>(Y);
    float4* __restrict__ ZF4 = reinterpret_cast<float4*>(Zf);
    float4* __restrict__ ZV4 = reinterpret_cast<float4*>(Zv);

    float Zm = 0.0f;     // filtered mean
    float Zr = 1.0f;     // filtered variance
    float ll = 0.0f;

#define STEP(s_, c_, y_, zf_, zv_)                                              \
        {                                                                       \
            float Zpred = fmaf(psi, Zm, fmaf(tS, (s_), fmaf(tC, (c_), tc0)));   \
            float Zpv   = fmaf(psi2, Zr, sigma2);                               \
            float logit = fmaf(bZ, Zpred, fmaf(oS, (s_), ob0));                 \
            logit = fminf(fmaxf(logit, -20.0f), 20.0f);                         \
            float e  = __expf(-logit);                                          \
            float p  = __fdividef(1.0f, 1.0f + e);                              \
            float pq = e * p * p;              /* p*(1-p) */                    \
            float hess = fmaf(bZ2, pq, 1e-6f);                                  \
            float Zpo  = __fdividef(Zpv, fmaf(Zpv, hess, 1.0f));                \
            float grad = ((y_) - p) * bZ;                                       \
            Zm = fmaf(Zpo, grad, Zpred);                                        \
            Zr = Zpo;                                                           \
            /* y in {0,1}: y*log(p+eps)+(1-y)*log(1-p+eps) == log(sel+eps) */   \
            float sel = ((y_) != 0.0f) ? p : (1.0f - p);                        \
            ll += __logf(sel + 1e-10f);                                         \
            (zf_) = Zm;                                                         \
            (zv_) = Zr;                                                         \
        }

// One half-chunk: 2 float4 per array loaded, 8 steps, 2+2 float4 stored.
#define HALF(goff)                                                              \
        {                                                                       \
            const float4 s0 = S4[(goff) + 0];                                   \
            const float4 s1 = S4[(goff) + 1];                                   \
            const float4 c0 = C4[(goff) + 0];                                   \
            const float4 c1 = C4[(goff) + 1];                                   \
            const float4 y0 = Y4[(goff) + 0];                                   \
            const float4 y1 = Y4[(goff) + 1];                                   \
            float4 zf0, zv0, zf1, zv1;                                          \
            STEP(s0.x, c0.x, y0.x, zf0.x, zv0.x);                               \
            STEP(s0.y, c0.y, y0.y, zf0.y, zv0.y);                               \
            STEP(s0.z, c0.z, y0.z, zf0.z, zv0.z);                               \
            STEP(s0.w, c0.w, y0.w, zf0.w, zv0.w);                               \
            STEP(s1.x, c1.x, y1.x, zf1.x, zv1.x);                               \
            STEP(s1.y, c1.y, y1.y, zf1.y, zv1.y);                               \
            STEP(s1.z, c1.z, y1.z, zf1.z, zv1.z);                               \
            STEP(s1.w, c1.w, y1.w, zf1.w, zv1.w);                               \
            ZF4[(goff) + 0] = zf0;                                              \
            ZF4[(goff) + 1] = zf1;                                              \
            ZV4[(goff) + 0] = zv0;                                              \
            ZV4[(goff) + 1] = zv1;                                              \
        }

    if (valid) {
        const size_t rbase = (size_t)row * (T_STEPS / 4);
        #pragma unroll 1
        for (int ch = 0; ch < NCH; ch++) {
            const size_t g = rbase + ch * 4;
            HALF(g);
            HALF(g + 2);
        }
    }
#undef HALF
#undef STEP

    // ---- deterministic block reduction of ll ----
    #pragma unroll
    for (int off = 16; off > 0; off >>= 1)
        ll += __shfl_down_sync(0xffffffffu, ll, off);

    if (lane == 0) wsum[wid] = ll;
    __syncthreads();

    if (tid == 0) {
        float v = 0.0f;
        #pragma unroll
        for (int w = 0; w < THREADS / 32; w++) v += wsum[w];
        g_part[blockIdx.x] = (double)v;
        __threadfence();
        unsigned int ticket = atomicAdd(&g_ticket, 1u);
        is_last = (ticket == gridDim.x - 1);
        if (is_last) g_ticket = 0;    // self-reset for replay launches
    }
    __syncthreads();

    // ---- last block: deterministic final reduction ----
    if (is_last) {
        double s = 0.0;
        for (int i = tid; i < (int)gridDim.x; i += THREADS)
            s += g_part[i];
        #pragma unroll
        for (int off = 16; off > 0; off >>= 1)
            s += __shfl_down_sync(0xffffffffu, s, off);
        if (lane == 0) dsum[wid] = s;
        __syncthreads();
        if (tid == 0) {
            double v = 0.0;
            #pragma unroll
            for (int w = 0; w < THREADS / 32; w++) v += dsum[w];
            *out_ll = (float)v;
        }
    }
}

extern "C" void kernel_launch(void* const* d_in, const int* in_sizes, int n_in,
                              void* d_out, int out_size)
{
    const float* G   = (const float*)d_in[0];
    const float* S   = (const float*)d_in[1];
    const float* C   = (const float*)d_in[2];
    const float* Y   = (const float*)d_in[3];
    const float* L   = (const float*)d_in[4];
    const float* psi = (const float*)d_in[5];
    const float* gS  = (const float*)d_in[6];
    const float* gC  = (const float*)d_in[7];
    const float* gG  = (const float*)d_in[8];
    const float* gGS = (const float*)d_in[9];
    const float* gGC = (const float*)d_in[10];
    const float* gLw = (const float*)d_in[11];
    const float* lsz = (const float*)d_in[12];
    const float* b0  = (const float*)d_in[13];
    const float* bZ  = (const float*)d_in[14];
    const float* bS  = (const float*)d_in[15];
    const float* bG  = (const float*)d_in[16];
    const float* bGS = (const float*)d_in[17];
    const float* bLw = (const float*)d_in[18];

    const int N = in_sizes[0];              // G is (N,1)
    const size_t NT = (size_t)N * T_STEPS;

    float* out = (float*)d_out;
    float* Zf  = out;                        // (N,T)
    float* Zv  = out + NT;                   // (N,T)
    float* llp = out + 2 * NT;               // scalar

    const int blocks = (N + THREADS - 1) / THREADS;

    hmm_filter_kernel<<<blocks, THREADS>>>(
        G, S, C, Y, L,
        psi, gS, gC, gG, gGS, gGC, gLw, lsz,
        b0, bZ, bS, bG, bGS, bLw,
        Zf, Zv, llp, N);
}

// round 6
// speedup vs baseline: 1.3438x; 1.3438x over previous
#include <cuda_runtime.h>
#include <math.h>
#include <stdint.h>

#define T_STEPS   64
#define TCH       16             // timesteps per chunk (64B per row per array)
#define NCH       (T_STEPS/TCH)  // 4 chunks
#define WARPS_PB  4
#define THREADS   (WARPS_PB*32)  // 128
#define FSTRIDE   5              // float4 per slab row (4 data + 1 pad): gcd(5,8)=1
#define SLAB4     (32*FSTRIDE)   // float4 per warp slab
#define MAXBLOCKS 4096

// Deterministic per-block log-likelihood partials + self-resetting ticket.
__device__ double       g_part[MAXBLOCKS];
__device__ unsigned int g_ticket;   // zero-init; last block resets to 0

__device__ __forceinline__ void cp_async16(uint32_t smem_dst, const void* gmem_src) {
    asm volatile("cp.async.ca.shared.global [%0], [%1], 16;\n"
                 :: "r"(smem_dst), "l"(gmem_src));
}
__device__ __forceinline__ void cp_async_commit_wait() {
    asm volatile("cp.async.commit_group;\n");
    asm volatile("cp.async.wait_group 0;\n" ::: "memory");
}

__global__ __launch_bounds__(THREADS, 7)
void hmm_filter_kernel(
    const float* __restrict__ G,   // (N,1)
    const float* __restrict__ S,   // (N,T)
    const float* __restrict__ C,   // (N,T)
    const float* __restrict__ Y,   // (N,T)
    const float* __restrict__ L,   // (N,3)
    const float* __restrict__ p_psi,
    const float* __restrict__ p_gS,
    const float* __restrict__ p_gC,
    const float* __restrict__ p_gG,
    const float* __restrict__ p_gGS,
    const float* __restrict__ p_gGC,
    const float* __restrict__ p_gLw,   // (1,3)
    const float* __restrict__ p_lsz,
    const float* __restrict__ p_b0,
    const float* __restrict__ p_bZ,
    const float* __restrict__ p_bS,
    const float* __restrict__ p_bG,
    const float* __restrict__ p_bGS,
    const float* __restrict__ p_bLw,   // (1,3)
    float* __restrict__ Zf,            // (N,T)
    float* __restrict__ Zv,            // (N,T)
    float* __restrict__ out_ll,
    int N)
{
    // Warp-private float4 slabs (16B-aligned rows; stride 5 -> conflict-free LDS.128).
    __shared__ float4 Sb[WARPS_PB][SLAB4];
    __shared__ float4 Cb[WARPS_PB][SLAB4];
    __shared__ float4 Yb[WARPS_PB][SLAB4];
    __shared__ float  wsum[WARPS_PB];
    __shared__ double dsum[WARPS_PB];
    __shared__ bool   is_last;

    // ---- scalar params ----
    const float psi  = __ldg(p_psi);
    const float gS   = __ldg(p_gS);
    const float gC   = __ldg(p_gC);
    const float gG   = __ldg(p_gG);
    const float gGS  = __ldg(p_gGS);
    const float gGC  = __ldg(p_gGC);
    const float lsz  = __ldg(p_lsz);
    const float b0   = __ldg(p_b0);
    const float bZ   = __ldg(p_bZ);
    const float bS   = __ldg(p_bS);
    const float bG   = __ldg(p_bG);
    const float bGS  = __ldg(p_bGS);
    const float gw0  = __ldg(p_gLw + 0), gw1 = __ldg(p_gLw + 1), gw2 = __ldg(p_gLw + 2);
    const float bw0  = __ldg(p_bLw + 0), bw1 = __ldg(p_bLw + 1), bw2 = __ldg(p_bLw + 2);

    const float sz     = expf(lsz);
    const float sigma2 = sz * sz;
    const float psi2   = psi * psi;
    const float bZ2    = bZ * bZ;

    const int tid   = threadIdx.x;
    const int lane  = tid & 31;
    const int wid   = tid >> 5;
    const int row0w = blockIdx.x * THREADS + wid * 32;  // warp's first row
    const int row   = row0w + lane;
    const bool valid = (row < N);

    float4* const sS = Sb[wid];
    float4* const sC = Cb[wid];
    float4* const sY = Yb[wid];
    const uint32_t aS = (uint32_t)__cvta_generic_to_shared(sS);
    const uint32_t aC = (uint32_t)__cvta_generic_to_shared(sC);
    const uint32_t aY = (uint32_t)__cvta_generic_to_shared(sY);

    // Per-row fused constants
    float tc0 = 0.f, tS = 0.f, tC = 0.f, ob0 = 0.f, oS = 0.f;
    if (valid) {
        const float Gn = __ldg(G + row);
        const float l0 = __ldg(L + 3 * (size_t)row + 0);
        const float l1 = __ldg(L + 3 * (size_t)row + 1);
        const float l2 = __ldg(L + 3 * (size_t)row + 2);
        const float gL = fmaf(gw0, l0, fmaf(gw1, l1, gw2 * l2));
        const float bL = fmaf(bw0, l0, fmaf(bw1, l1, bw2 * l2));
        tc0 = fmaf(gG, Gn, gL);
        tS  = fmaf(gGS, Gn, gS);
        tC  = fmaf(gGC, Gn, gC);
        ob0 = fmaf(bG, Gn, b0) + bL;
        oS  = fmaf(bGS, Gn, bS);
    }

    const float4* __restrict__ S4  = reinterpret_cast<const float4*>(S);
    const float4* __restrict__ C4  = reinterpret_cast<const float4*>(C);
    const float4* __restrict__ Y4  = reinterpret_cast<const float4*>(Y);
    float4* __restrict__ ZF4 = reinterpret_cast<float4*>(Zf);
    float4* __restrict__ ZV4 = reinterpret_cast<float4*>(Zv);

    float Zm = 0.0f;     // filtered mean
    float Zr = 1.0f;     // filtered variance
    float ll = 0.0f;

#define STEP(s_, c_, y_, zf_, zv_)                                              \
        {                                                                       \
            float Zpred = fmaf(psi, Zm, fmaf(tS, (s_), fmaf(tC, (c_), tc0)));   \
            float Zpv   = fmaf(psi2, Zr, sigma2);                               \
            float logit = fmaf(bZ, Zpred, fmaf(oS, (s_), ob0));                 \
            logit = fminf(fmaxf(logit, -20.0f), 20.0f);                         \
            float e  = __expf(-logit);                                          \
            float p  = __fdividef(1.0f, 1.0f + e);                              \
            float pq = e * p * p;              /* p*(1-p) */                    \
            float hess = fmaf(bZ2, pq, 1e-6f);                                  \
            float Zpo  = __fdividef(Zpv, fmaf(Zpv, hess, 1.0f));                \
            float grad = ((y_) - p) * bZ;                                       \
            Zm = fmaf(Zpo, grad, Zpred);                                        \
            Zr = Zpo;                                                           \
            /* y in {0,1}: y*log(p+eps)+(1-y)*log(1-p+eps) == log(sel+eps) */   \
            float sel = ((y_) != 0.0f) ? p : (1.0f - p);                        \
            ll += __logf(sel + 1e-10f);                                         \
            (zf_) = Zm;                                                         \
            (zv_) = Zr;                                                         \
        }

    #pragma unroll 1
    for (int ch = 0; ch < NCH; ch++) {
        // ---- staged async load: warp covers 8 rows x 64B contiguous per step ----
        #pragma unroll
        for (int k = 0; k < 4; k++) {
            const int f = lane + k * 32;   // 0..127
            const int r = f >> 2;          // row within warp
            const int j = f & 3;           // float4 within 64B granule
            const int rr = row0w + r;
            if (rr < N) {
                const size_t g = (size_t)rr * (T_STEPS / 4) + ch * 4 + j;
                const uint32_t b = (uint32_t)(r * FSTRIDE + j) * 16u;
                cp_async16(aS + b, S4 + g);
                cp_async16(aC + b, C4 + g);
                cp_async16(aY + b, Y4 + g);
            }
        }
        cp_async_commit_wait();
        __syncwarp();

        // ---- compute: conflict-free LDS.128, overwrite sS/sC with Zf/Zv ----
        if (valid) {
            const int base = lane * FSTRIDE;
            #pragma unroll
            for (int q = 0; q < 4; q++) {
                const float4 s4 = sS[base + q];
                const float4 c4 = sC[base + q];
                const float4 y4 = sY[base + q];
                float4 zf4, zv4;
                STEP(s4.x, c4.x, y4.x, zf4.x, zv4.x);
                STEP(s4.y, c4.y, y4.y, zf4.y, zv4.y);
                STEP(s4.z, c4.z, y4.z, zf4.z, zv4.z);
                STEP(s4.w, c4.w, y4.w, zf4.w, zv4.w);
                sS[base + q] = zf4;
                sC[base + q] = zv4;
            }
        }
        __syncwarp();

        // ---- coalesced flush: LDS.128 + STG.128, 8 rows x 64B per step ----
        #pragma unroll
        for (int k = 0; k < 4; k++) {
            const int f = lane + k * 32;
            const int r = f >> 2;
            const int j = f & 3;
            const int rr = row0w + r;
            if (rr < N) {
                const int b = r * FSTRIDE + j;
                const float4 zf4 = sS[b];
                const float4 zv4 = sC[b];
                const size_t g = (size_t)rr * (T_STEPS / 4) + ch * 4 + j;
                ZF4[g] = zf4;
                ZV4[g] = zv4;
            }
        }
        __syncwarp();   // flush reads done before next chunk's cp.async overwrites
    }
#undef STEP

    // ---- deterministic block reduction of ll ----
    #pragma unroll
    for (int off = 16; off > 0; off >>= 1)
        ll += __shfl_down_sync(0xffffffffu, ll, off);

    if (lane == 0) wsum[wid] = ll;
    __syncthreads();

    if (tid == 0) {
        float v = 0.0f;
        #pragma unroll
        for (int w = 0; w < WARPS_PB; w++) v += wsum[w];
        g_part[blockIdx.x] = (double)v;
        __threadfence();
        unsigned int ticket = atomicAdd(&g_ticket, 1u);
        is_last = (ticket == gridDim.x - 1);
        if (is_last) g_ticket = 0;    // self-reset for replay launches
    }
    __syncthreads();

    // ---- last block: deterministic final reduction ----
    if (is_last) {
        double s = 0.0;
        for (int i = tid; i < (int)gridDim.x; i += THREADS)
            s += g_part[i];
        #pragma unroll
        for (int off = 16; off > 0; off >>= 1)
            s += __shfl_down_sync(0xffffffffu, s, off);
        if (lane == 0) dsum[wid] = s;
        __syncthreads();
        if (tid == 0) {
            double v = 0.0;
            #pragma unroll
            for (int w = 0; w < WARPS_PB; w++) v += dsum[w];
            *out_ll = (float)v;
        }
    }
}

extern "C" void kernel_launch(void* const* d_in, const int* in_sizes, int n_in,
                              void* d_out, int out_size)
{
    const float* G   = (const float*)d_in[0];
    const float* S   = (const float*)d_in[1];
    const float* C   = (const float*)d_in[2];
    const float* Y   = (const float*)d_in[3];
    const float* L   = (const float*)d_in[4];
    const float* psi = (const float*)d_in[5];
    const float* gS  = (const float*)d_in[6];
    const float* gC  = (const float*)d_in[7];
    const float* gG  = (const float*)d_in[8];
    const float* gGS = (const float*)d_in[9];
    const float* gGC = (const float*)d_in[10];
    const float* gLw = (const float*)d_in[11];
    const float* lsz = (const float*)d_in[12];
    const float* b0  = (const float*)d_in[13];
    const float* bZ  = (const float*)d_in[14];
    const float* bS  = (const float*)d_in[15];
    const float* bG  = (const float*)d_in[16];
    const float* bGS = (const float*)d_in[17];
    const float* bLw = (const float*)d_in[18];

    const int N = in_sizes[0];              // G is (N,1)
    const size_t NT = (size_t)N * T_STEPS;

    float* out = (float*)d_out;
    float* Zf  = out;                        // (N,T)
    float* Zv  = out + NT;                   // (N,T)
    float* llp = out + 2 * NT;               // scalar

    const int blocks = (N + THREADS - 1) / THREADS;

    hmm_filter_kernel<<<blocks, THREADS>>>(
        G, S, C, Y, L,
        psi, gS, gC, gG, gGS, gGC, gLw, lsz,
        b0, bZ, bS, bG, bGS, bLw,
        Zf, Zv, llp, N);
}

// round 7
// speedup vs baseline: 1.3700x; 1.0195x over previous
#include <cuda_runtime.h>
#include <math.h>
#include <stdint.h>

#define T_STEPS   64
#define TCH       16             // timesteps per chunk (64B per row per array)
#define NCH       (T_STEPS/TCH)  // 4 chunks
#define WARPS_PB  2
#define THREADS   (WARPS_PB*32)  // 64
#define FSTRIDE   5              // float4 per slab row (4 data + 1 pad): gcd(5,8)=1
#define SLAB4     (32*FSTRIDE)   // float4 per warp slab per buffer
#define MAXBLOCKS 8192

// Deterministic per-block log-likelihood partials + self-resetting ticket.
__device__ double       g_part[MAXBLOCKS];
__device__ unsigned int g_ticket;   // zero-init; last block resets to 0

__device__ __forceinline__ void cp_async16(uint32_t smem_dst, const void* gmem_src) {
    asm volatile("cp.async.ca.shared.global [%0], [%1], 16;\n"
                 :: "r"(smem_dst), "l"(gmem_src));
}
__device__ __forceinline__ void cp_async_commit() {
    asm volatile("cp.async.commit_group;\n");
}
template <int NLeft>
__device__ __forceinline__ void cp_async_wait() {
    asm volatile("cp.async.wait_group %0;\n" :: "n"(NLeft) : "memory");
}

__global__ __launch_bounds__(THREADS)
void hmm_filter_kernel(
    const float* __restrict__ G,   // (N,1)
    const float* __restrict__ S,   // (N,T)
    const float* __restrict__ C,   // (N,T)
    const float* __restrict__ Y,   // (N,T)
    const float* __restrict__ L,   // (N,3)
    const float* __restrict__ p_psi,
    const float* __restrict__ p_gS,
    const float* __restrict__ p_gC,
    const float* __restrict__ p_gG,
    const float* __restrict__ p_gGS,
    const float* __restrict__ p_gGC,
    const float* __restrict__ p_gLw,   // (1,3)
    const float* __restrict__ p_lsz,
    const float* __restrict__ p_b0,
    const float* __restrict__ p_bZ,
    const float* __restrict__ p_bS,
    const float* __restrict__ p_bG,
    const float* __restrict__ p_bGS,
    const float* __restrict__ p_bLw,   // (1,3)
    float* __restrict__ Zf,            // (N,T)
    float* __restrict__ Zv,            // (N,T)
    float* __restrict__ out_ll,
    int N)
{
    // Warp-private double-buffered float4 slabs. Stride 5 -> conflict-free LDS.128.
    __shared__ float4 Sb[WARPS_PB][2][SLAB4];
    __shared__ float4 Cb[WARPS_PB][2][SLAB4];
    __shared__ float4 Yb[WARPS_PB][2][SLAB4];
    __shared__ float  wsum[WARPS_PB];
    __shared__ double dsum[WARPS_PB];
    __shared__ bool   is_last;

    // ---- scalar params ----
    const float psi  = __ldg(p_psi);
    const float gS   = __ldg(p_gS);
    const float gC   = __ldg(p_gC);
    const float gG   = __ldg(p_gG);
    const float gGS  = __ldg(p_gGS);
    const float gGC  = __ldg(p_gGC);
    const float lsz  = __ldg(p_lsz);
    const float b0   = __ldg(p_b0);
    const float bZ   = __ldg(p_bZ);
    const float bS   = __ldg(p_bS);
    const float bG   = __ldg(p_bG);
    const float bGS  = __ldg(p_bGS);
    const float gw0  = __ldg(p_gLw + 0), gw1 = __ldg(p_gLw + 1), gw2 = __ldg(p_gLw + 2);
    const float bw0  = __ldg(p_bLw + 0), bw1 = __ldg(p_bLw + 1), bw2 = __ldg(p_bLw + 2);

    const float sz     = expf(lsz);
    const float sigma2 = sz * sz;
    const float psi2   = psi * psi;
    const float bZ2    = bZ * bZ;

    const int tid   = threadIdx.x;
    const int lane  = tid & 31;
    const int wid   = tid >> 5;
    const int row0w = blockIdx.x * THREADS + wid * 32;  // warp's first row
    const int row   = row0w + lane;
    const bool valid = (row < N);

    const uint32_t aS0 = (uint32_t)__cvta_generic_to_shared(&Sb[wid][0][0]);
    const uint32_t aS1 = (uint32_t)__cvta_generic_to_shared(&Sb[wid][1][0]);
    const uint32_t aC0 = (uint32_t)__cvta_generic_to_shared(&Cb[wid][0][0]);
    const uint32_t aC1 = (uint32_t)__cvta_generic_to_shared(&Cb[wid][1][0]);
    const uint32_t aY0 = (uint32_t)__cvta_generic_to_shared(&Yb[wid][0][0]);
    const uint32_t aY1 = (uint32_t)__cvta_generic_to_shared(&Yb[wid][1][0]);

    // Per-row fused constants
    float tc0 = 0.f, tS = 0.f, tC = 0.f, ob0 = 0.f, oS = 0.f;
    if (valid) {
        const float Gn = __ldg(G + row);
        const float l0 = __ldg(L + 3 * (size_t)row + 0);
        const float l1 = __ldg(L + 3 * (size_t)row + 1);
        const float l2 = __ldg(L + 3 * (size_t)row + 2);
        const float gL = fmaf(gw0, l0, fmaf(gw1, l1, gw2 * l2));
        const float bL = fmaf(bw0, l0, fmaf(bw1, l1, bw2 * l2));
        tc0 = fmaf(gG, Gn, gL);
        tS  = fmaf(gGS, Gn, gS);
        tC  = fmaf(gGC, Gn, gC);
        ob0 = fmaf(bG, Gn, b0) + bL;
        oS  = fmaf(bGS, Gn, bS);
    }

    const float4* __restrict__ S4  = reinterpret_cast<const float4*>(S);
    const float4* __restrict__ C4  = reinterpret_cast<const float4*>(C);
    const float4* __restrict__ Y4  = reinterpret_cast<const float4*>(Y);
    float4* __restrict__ ZF4 = reinterpret_cast<float4*>(Zf);
    float4* __restrict__ ZV4 = reinterpret_cast<float4*>(Zv);

    // Staging geometry for this thread (fixed across chunks):
    // thread covers row r = lane>>2, float4 j = lane&3, for k in {0,1,2,3}: r += 8k.
    const int r_st = lane >> 2;
    const int j_st = lane & 3;

    float Zm = 0.0f;     // filtered mean
    float Zr = 1.0f;     // filtered variance
    float ll = 0.0f;

#define PREFETCH(ch_, aS_, aC_, aY_)                                            \
        {                                                                       \
            _Pragma("unroll")                                                   \
            for (int k = 0; k < 4; k++) {                                       \
                const int r = r_st + k * 8;                                     \
                const int rr = row0w + r;                                       \
                if (rr < N) {                                                   \
                    const size_t g = (size_t)rr * (T_STEPS / 4) + (ch_) * 4 + j_st; \
                    const uint32_t b = (uint32_t)(r * FSTRIDE + j_st) * 16u;    \
                    cp_async16((aS_) + b, S4 + g);                              \
                    cp_async16((aC_) + b, C4 + g);                              \
                    cp_async16((aY_) + b, Y4 + g);                              \
                }                                                               \
            }                                                                   \
            cp_async_commit();                                                  \
        }

#define STEP(s_, c_, y_, zf_, zv_)                                              \
        {                                                                       \
            float Zpred = fmaf(psi, Zm, fmaf(tS, (s_), fmaf(tC, (c_), tc0)));   \
            float Zpv   = fmaf(psi2, Zr, sigma2);                               \
            float logit = fmaf(bZ, Zpred, fmaf(oS, (s_), ob0));                 \
            logit = fminf(fmaxf(logit, -20.0f), 20.0f);                         \
            float e  = __expf(-logit);                                          \
            float p  = __fdividef(1.0f, 1.0f + e);                              \
            float pq = e * p * p;              /* p*(1-p) */                    \
            float hess = fmaf(bZ2, pq, 1e-6f);                                  \
            float Zpo  = __fdividef(Zpv, fmaf(Zpv, hess, 1.0f));                \
            float grad = ((y_) - p) * bZ;                                       \
            Zm = fmaf(Zpo, grad, Zpred);                                        \
            Zr = Zpo;                                                           \
            /* y in {0,1}: y*log(p+eps)+(1-y)*log(1-p+eps) == log(sel+eps) */   \
            float sel = ((y_) != 0.0f) ? p : (1.0f - p);                        \
            ll += __logf(sel + 1e-10f);                                         \
            (zf_) = Zm;                                                         \
            (zv_) = Zr;                                                         \
        }

// Compute 16 steps from buffer buf_, overwriting its S/C slots with Zf/Zv.
#define COMPUTE(buf_)                                                           \
        if (valid) {                                                            \
            float4* const cS = &Sb[wid][buf_][0];                               \
            float4* const cC = &Cb[wid][buf_][0];                               \
            float4* const cY = &Yb[wid][buf_][0];                               \
            const int base = lane * FSTRIDE;                                    \
            _Pragma("unroll")                                                   \
            for (int q = 0; q < 4; q++) {                                       \
                const float4 s4 = cS[base + q];                                 \
                const float4 c4 = cC[base + q];                                 \
                const float4 y4 = cY[base + q];                                 \
                float4 zf4, zv4;                                                \
                STEP(s4.x, c4.x, y4.x, zf4.x, zv4.x);                           \
                STEP(s4.y, c4.y, y4.y, zf4.y, zv4.y);                           \
                STEP(s4.z, c4.z, y4.z, zf4.z, zv4.z);                           \
                STEP(s4.w, c4.w, y4.w, zf4.w, zv4.w);                           \
                cS[base + q] = zf4;                                             \
                cC[base + q] = zv4;                                             \
            }                                                                   \
        }

// Flush buffer buf_'s S/C slots (now Zf/Zv) to gmem, coalesced.
#define FLUSH(ch_, buf_)                                                        \
        {                                                                       \
            float4* const cS = &Sb[wid][buf_][0];                               \
            float4* const cC = &Cb[wid][buf_][0];                               \
            _Pragma("unroll")                                                   \
            for (int k = 0; k < 4; k++) {                                       \
                const int r = r_st + k * 8;                                     \
                const int rr = row0w + r;                                       \
                if (rr < N) {                                                   \
                    const int b = r * FSTRIDE + j_st;                           \
                    const float4 zf4 = cS[b];                                   \
                    const float4 zv4 = cC[b];                                   \
                    const size_t g = (size_t)rr * (T_STEPS / 4) + (ch_) * 4 + j_st; \
                    ZF4[g] = zf4;                                               \
                    ZV4[g] = zv4;                                               \
                }                                                               \
            }                                                                   \
        }

    // ---- software pipeline: prefetch ch+1 while computing ch ----
    PREFETCH(0, aS0, aC0, aY0);                    // group for chunk 0

    // ch = 0
    PREFETCH(1, aS1, aC1, aY1);                    // group for chunk 1
    cp_async_wait<1>();  __syncwarp();             // chunk 0 ready
    COMPUTE(0);          __syncwarp();
    FLUSH(0, 0);         __syncwarp();

    // ch = 1
    PREFETCH(2, aS0, aC0, aY0);                    // group for chunk 2 (buf 0 flushed)
    cp_async_wait<1>();  __syncwarp();             // chunk 1 ready
    COMPUTE(1);          __syncwarp();
    FLUSH(1, 1);         __syncwarp();

    // ch = 2
    PREFETCH(3, aS1, aC1, aY1);                    // group for chunk 3 (buf 1 flushed)
    cp_async_wait<1>();  __syncwarp();             // chunk 2 ready
    COMPUTE(0);          __syncwarp();
    FLUSH(2, 0);         __syncwarp();

    // ch = 3
    cp_async_wait<0>();  __syncwarp();             // chunk 3 ready
    COMPUTE(1);          __syncwarp();
    FLUSH(3, 1);

#undef FLUSH
#undef COMPUTE
#undef STEP
#undef PREFETCH

    // ---- deterministic block reduction of ll ----
    #pragma unroll
    for (int off = 16; off > 0; off >>= 1)
        ll += __shfl_down_sync(0xffffffffu, ll, off);

    if (lane == 0) wsum[wid] = ll;
    __syncthreads();

    if (tid == 0) {
        float v = 0.0f;
        #pragma unroll
        for (int w = 0; w < WARPS_PB; w++) v += wsum[w];
        g_part[blockIdx.x] = (double)v;
        __threadfence();
        unsigned int ticket = atomicAdd(&g_ticket, 1u);
        is_last = (ticket == gridDim.x - 1);
        if (is_last) g_ticket = 0;    // self-reset for replay launches
    }
    __syncthreads();

    // ---- last block: deterministic final reduction ----
    if (is_last) {
        double s = 0.0;
        for (int i = tid; i < (int)gridDim.x; i += THREADS)
            s += g_part[i];
        #pragma unroll
        for (int off = 16; off > 0; off >>= 1)
            s += __shfl_down_sync(0xffffffffu, s, off);
        if (lane == 0) dsum[wid] = s;
        __syncthreads();
        if (tid == 0) {
            double v = 0.0;
            #pragma unroll
            for (int w = 0; w < WARPS_PB; w++) v += dsum[w];
            *out_ll = (float)v;
        }
    }
}

extern "C" void kernel_launch(void* const* d_in, const int* in_sizes, int n_in,
                              void* d_out, int out_size)
{
    const float* G   = (const float*)d_in[0];
    const float* S   = (const float*)d_in[1];
    const float* C   = (const float*)d_in[2];
    const float* Y   = (const float*)d_in[3];
    const float* L   = (const float*)d_in[4];
    const float* psi = (const float*)d_in[5];
    const float* gS  = (const float*)d_in[6];
    const float* gC  = (const float*)d_in[7];
    const float* gG  = (const float*)d_in[8];
    const float* gGS = (const float*)d_in[9];
    const float* gGC = (const float*)d_in[10];
    const float* gLw = (const float*)d_in[11];
    const float* lsz = (const float*)d_in[12];
    const float* b0  = (const float*)d_in[13];
    const float* bZ  = (const float*)d_in[14];
    const float* bS  = (const float*)d_in[15];
    const float* bG  = (const float*)d_in[16];
    const float* bGS = (const float*)d_in[17];
    const float* bLw = (const float*)d_in[18];

    const int N = in_sizes[0];              // G is (N,1)
    const size_t NT = (size_t)N * T_STEPS;

    float* out = (float*)d_out;
    float* Zf  = out;                        // (N,T)
    float* Zv  = out + NT;                   // (N,T)
    float* llp = out + 2 * NT;               // scalar

    const int blocks = (N + THREADS - 1) / THREADS;

    hmm_filter_kernel<<<blocks, THREADS>>>(
        G, S, C, Y, L,
        psi, gS, gC, gG, gGS, gGC, gLw, lsz,
        b0, bZ, bS, bG, bGS, bLw,
        Zf, Zv, llp, N);
}

// round 8
// speedup vs baseline: 1.6464x; 1.2018x over previous
#include <cuda_runtime.h>
#include <cuda.h>
#include <math.h>
#include <stdint.h>

#define T_STEPS   64
#define ROWS      64             // rows per CTA (= threads)
#define THREADS   64
#define TILE_B    8192           // 64 rows * 128B (32 floats) per array per half
#define HALF_TX   (3 * TILE_B)   // expect_tx bytes per half (S+C+Y)
#define SMEM_DYN  (1024 + 6 * TILE_B + 64)
#define MAXBLOCKS 8192

// Deterministic per-block ll partials + self-resetting ticket.
__device__ double       g_part[MAXBLOCKS];
__device__ unsigned int g_ticket;

// ---------------- PTX helpers ----------------
__device__ __forceinline__ void mbar_init(uint32_t a, uint32_t cnt) {
    asm volatile("mbarrier.init.shared.b64 [%0], %1;" :: "r"(a), "r"(cnt) : "memory");
}
__device__ __forceinline__ void mbar_expect(uint32_t a, uint32_t bytes) {
    asm volatile("mbarrier.arrive.expect_tx.shared.b64 _, [%0], %1;"
                 :: "r"(a), "r"(bytes) : "memory");
}
__device__ __forceinline__ void mbar_wait(uint32_t a, uint32_t parity) {
    uint32_t done;
    asm volatile(
        "{\n\t.reg .pred p;\n\t"
        "mbarrier.try_wait.parity.acquire.cta.shared::cta.b64 p, [%1], %2;\n\t"
        "selp.b32 %0, 1, 0, p;\n\t}"
        : "=r"(done) : "r"(a), "r"(parity) : "memory");
    if (!done) {
        asm volatile(
            "{\n\t.reg .pred P1;\n\t"
            "W_%=:\n\t"
            "mbarrier.try_wait.parity.acquire.cta.shared::cta.b64 P1, [%0], %1, 0x989680;\n\t"
            "@P1 bra.uni D_%=;\n\t"
            "bra.uni W_%=;\n\t"
            "D_%=:\n\t}" :: "r"(a), "r"(parity) : "memory");
    }
}
__device__ __forceinline__ void tma_load2d(uint32_t dst, const CUtensorMap* m,
                                           int c0, int c1, uint32_t mb) {
    asm volatile(
        "cp.async.bulk.tensor.2d.shared::cta.global.tile.mbarrier::complete_tx::bytes "
        "[%0], [%1, {%2, %3}], [%4];"
        :: "r"(dst), "l"(m), "r"(c0), "r"(c1), "r"(mb) : "memory");
}
__device__ __forceinline__ void tma_store2d(const CUtensorMap* m, int c0, int c1,
                                            uint32_t src) {
    asm volatile(
        "cp.async.bulk.tensor.2d.global.shared::cta.tile.bulk_group "
        "[%0, {%1, %2}], [%3];"
        :: "l"(m), "r"(c0), "r"(c1), "r"(src) : "memory");
}
__device__ __forceinline__ void fence_proxy_async_cta() {
    asm volatile("fence.proxy.async.shared::cta;" ::: "memory");
}
__device__ __forceinline__ void tma_commit() {
    asm volatile("cp.async.bulk.commit_group;" ::: "memory");
}
__device__ __forceinline__ void tma_wait_read0() {
    asm volatile("cp.async.bulk.wait_group.read 0;" ::: "memory");
}

__global__ __launch_bounds__(THREADS)
void hmm_filter_tma(
    const __grid_constant__ CUtensorMap tmS,
    const __grid_constant__ CUtensorMap tmC,
    const __grid_constant__ CUtensorMap tmY,
    const __grid_constant__ CUtensorMap tmZf,
    const __grid_constant__ CUtensorMap tmZv,
    const float* __restrict__ G,   // (N,1)
    const float* __restrict__ L,   // (N,3)
    const float* __restrict__ p_psi,
    const float* __restrict__ p_gS,
    const float* __restrict__ p_gC,
    const float* __restrict__ p_gG,
    const float* __restrict__ p_gGS,
    const float* __restrict__ p_gGC,
    const float* __restrict__ p_gLw,
    const float* __restrict__ p_lsz,
    const float* __restrict__ p_b0,
    const float* __restrict__ p_bZ,
    const float* __restrict__ p_bS,
    const float* __restrict__ p_bG,
    const float* __restrict__ p_bGS,
    const float* __restrict__ p_bLw,
    float* __restrict__ out_ll,
    int N)
{
    extern __shared__ char dsm[];
    __shared__ float  wsum[THREADS / 32];
    __shared__ double dsum[THREADS / 32];
    __shared__ bool   is_last;

    const uint32_t sb = (uint32_t)__cvta_generic_to_shared(dsm);
    const uint32_t A  = (sb + 1023u) & ~1023u;     // 1KB-aligned tile base
    char* const Ag    = dsm + (A - sb);

    float4* const S0 = (float4*)(Ag + 0 * TILE_B);
    float4* const C0 = (float4*)(Ag + 1 * TILE_B);
    float4* const Y0 = (float4*)(Ag + 2 * TILE_B);
    float4* const S1 = (float4*)(Ag + 3 * TILE_B);
    float4* const C1 = (float4*)(Ag + 4 * TILE_B);
    float4* const Y1 = (float4*)(Ag + 5 * TILE_B);
    const uint32_t mb0 = A + 6 * TILE_B;
    const uint32_t mb1 = mb0 + 8;

    const int tid  = threadIdx.x;
    const int lane = tid & 31;
    const int wid  = tid >> 5;
    const int row0 = blockIdx.x * ROWS;
    const int row  = row0 + tid;
    const bool valid = (row < N);

    // ---- kick off all TMA loads ASAP ----
    if (tid == 0) { mbar_init(mb0, 1); mbar_init(mb1, 1); }
    __syncthreads();
    if (tid == 0) {
        mbar_expect(mb0, HALF_TX);
        tma_load2d(A + 0 * TILE_B, &tmS, 0, row0, mb0);
        tma_load2d(A + 1 * TILE_B, &tmC, 0, row0, mb0);
        tma_load2d(A + 2 * TILE_B, &tmY, 0, row0, mb0);
        mbar_expect(mb1, HALF_TX);
        tma_load2d(A + 3 * TILE_B, &tmS, 32, row0, mb1);
        tma_load2d(A + 4 * TILE_B, &tmC, 32, row0, mb1);
        tma_load2d(A + 5 * TILE_B, &tmY, 32, row0, mb1);
    }

    // ---- scalar params (overlap with TMA latency) ----
    const float psi  = __ldg(p_psi);
    const float gS   = __ldg(p_gS);
    const float gC   = __ldg(p_gC);
    const float gG   = __ldg(p_gG);
    const float gGS  = __ldg(p_gGS);
    const float gGC  = __ldg(p_gGC);
    const float lsz  = __ldg(p_lsz);
    const float b0   = __ldg(p_b0);
    const float bZ   = __ldg(p_bZ);
    const float bS   = __ldg(p_bS);
    const float bG   = __ldg(p_bG);
    const float bGS  = __ldg(p_bGS);
    const float gw0  = __ldg(p_gLw + 0), gw1 = __ldg(p_gLw + 1), gw2 = __ldg(p_gLw + 2);
    const float bw0  = __ldg(p_bLw + 0), bw1 = __ldg(p_bLw + 1), bw2 = __ldg(p_bLw + 2);

    const float sz     = expf(lsz);
    const float sigma2 = sz * sz;
    const float psi2   = psi * psi;
    const float bZ2    = bZ * bZ;

    float tc0 = 0.f, tS = 0.f, tC = 0.f, ob0 = 0.f, oS = 0.f;
    if (valid) {
        const float Gn = __ldg(G + row);
        const float l0 = __ldg(L + 3 * (size_t)row + 0);
        const float l1 = __ldg(L + 3 * (size_t)row + 1);
        const float l2 = __ldg(L + 3 * (size_t)row + 2);
        const float gL = fmaf(gw0, l0, fmaf(gw1, l1, gw2 * l2));
        const float bL = fmaf(bw0, l0, fmaf(bw1, l1, bw2 * l2));
        tc0 = fmaf(gG, Gn, gL);
        tS  = fmaf(gGS, Gn, gS);
        tC  = fmaf(gGC, Gn, gC);
        ob0 = fmaf(bG, Gn, b0) + bL;
        oS  = fmaf(bGS, Gn, bS);
    }

    float Zm = 0.0f;
    float Zr = 1.0f;
    float ll = 0.0f;

#define STEP(s_, c_, y_, zf_, zv_)                                              \
        {                                                                       \
            float Zpred = fmaf(psi, Zm, fmaf(tS, (s_), fmaf(tC, (c_), tc0)));   \
            float Zpv   = fmaf(psi2, Zr, sigma2);                               \
            float logit = fmaf(bZ, Zpred, fmaf(oS, (s_), ob0));                 \
            logit = fminf(fmaxf(logit, -20.0f), 20.0f);                         \
            float e  = __expf(-logit);                                          \
            float p  = __fdividef(1.0f, 1.0f + e);                              \
            float pq = e * p * p;              /* p*(1-p) */                    \
            float hess = fmaf(bZ2, pq, 1e-6f);                                  \
            float Zpo  = __fdividef(Zpv, fmaf(Zpv, hess, 1.0f));                \
            float grad = ((y_) - p) * bZ;                                       \
            Zm = fmaf(Zpo, grad, Zpred);                                        \
            Zr = Zpo;                                                           \
            float sel = ((y_) != 0.0f) ? p : (1.0f - p);                        \
            ll += __logf(sel + 1e-10f);                                         \
            (zf_) = Zm;                                                         \
            (zv_) = Zr;                                                         \
        }

    // SW128 within-tile addressing: row r (0..63), float4 q (0..7):
    //   idx = r*8 + (q ^ (r & 7))   (4-way spread == LDS.128 structural floor)
    const int rb = tid * 8;
    const int rx = tid & 7;

#define COMPUTE_HALF(Sp_, Cp_, Yp_)                                             \
        {                                                                       \
            _Pragma("unroll")                                                   \
            for (int q = 0; q < 8; q++) {                                       \
                const int idx = rb + (q ^ rx);                                  \
                const float4 s4 = (Sp_)[idx];                                   \
                const float4 c4 = (Cp_)[idx];                                   \
                const float4 y4 = (Yp_)[idx];                                   \
                float4 zf4, zv4;                                                \
                STEP(s4.x, c4.x, y4.x, zf4.x, zv4.x);                           \
                STEP(s4.y, c4.y, y4.y, zf4.y, zv4.y);                           \
                STEP(s4.z, c4.z, y4.z, zf4.z, zv4.z);                           \
                STEP(s4.w, c4.w, y4.w, zf4.w, zv4.w);                           \
                (Sp_)[idx] = zf4;   /* Zf overwrites S slot */                  \
                (Cp_)[idx] = zv4;   /* Zv overwrites C slot */                  \
            }                                                                   \
        }

    // ---- half 0 (t = 0..31) ----
    mbar_wait(mb0, 0);
    COMPUTE_HALF(S0, C0, Y0);
    __syncthreads();
    if (tid == 0) {
        fence_proxy_async_cta();
        tma_store2d(&tmZf, 0, row0, A + 0 * TILE_B);
        tma_store2d(&tmZv, 0, row0, A + 1 * TILE_B);
        tma_commit();
    }

    // ---- half 1 (t = 32..63) ----
    mbar_wait(mb1, 0);
    COMPUTE_HALF(S1, C1, Y1);
    __syncthreads();
    if (tid == 0) {
        fence_proxy_async_cta();
        tma_store2d(&tmZf, 32, row0, A + 3 * TILE_B);
        tma_store2d(&tmZv, 32, row0, A + 4 * TILE_B);
        tma_commit();
        tma_wait_read0();   // smem must stay valid until bulk reads complete
    }

#undef COMPUTE_HALF
#undef STEP

    // ---- deterministic ll reduction ----
    if (!valid) ll = 0.0f;
    #pragma unroll
    for (int off = 16; off > 0; off >>= 1)
        ll += __shfl_down_sync(0xffffffffu, ll, off);
    if (lane == 0) wsum[wid] = ll;
    __syncthreads();

    if (tid == 0) {
        float v = wsum[0] + wsum[1];
        g_part[blockIdx.x] = (double)v;
        __threadfence();
        unsigned int ticket = atomicAdd(&g_ticket, 1u);
        is_last = (ticket == gridDim.x - 1);
        if (is_last) g_ticket = 0;   // self-reset for graph replays
    }
    __syncthreads();

    if (is_last) {
        double s = 0.0;
        for (int i = tid; i < (int)gridDim.x; i += THREADS)
            s += g_part[i];
        #pragma unroll
        for (int off = 16; off > 0; off >>= 1)
            s += __shfl_down_sync(0xffffffffu, s, off);
        if (lane == 0) dsum[wid] = s;
        __syncthreads();
        if (tid == 0) *out_ll = (float)(dsum[0] + dsum[1]);
    }
}

// ---------------- host side ----------------
typedef CUresult (*EncFn)(CUtensorMap*, CUtensorMapDataType, cuuint32_t, void*,
                          const cuuint64_t*, const cuuint64_t*, const cuuint32_t*,
                          const cuuint32_t*, CUtensorMapInterleave, CUtensorMapSwizzle,
                          CUtensorMapL2promotion, CUtensorMapFloatOOBfill);

static EncFn get_encoder()
{
    void* fp = nullptr;
    cudaDriverEntryPointQueryResult st;
#if CUDART_VERSION >= 12050
    cudaGetDriverEntryPointByVersion("cuTensorMapEncodeTiled", &fp, 12000,
                                     cudaEnableDefault, &st);
#else
    cudaGetDriverEntryPoint("cuTensorMapEncodeTiled", &fp, cudaEnableDefault, &st);
#endif
    return (EncFn)fp;
}

static void make_map(EncFn enc, CUtensorMap* m, const void* base, int N)
{
    cuuint64_t dims[2]    = {(cuuint64_t)T_STEPS, (cuuint64_t)N};
    cuuint64_t strides[1] = {(cuuint64_t)T_STEPS * 4};   // 256B row stride
    cuuint32_t box[2]     = {32u, (cuuint32_t)ROWS};     // 128B x 64 rows
    cuuint32_t es[2]      = {1u, 1u};
    enc(m, CU_TENSOR_MAP_DATA_TYPE_FLOAT32, 2, (void*)base,
        dims, strides, box, es,
        CU_TENSOR_MAP_INTERLEAVE_NONE, CU_TENSOR_MAP_SWIZZLE_128B,
        CU_TENSOR_MAP_L2_PROMOTION_L2_128B, CU_TENSOR_MAP_FLOAT_OOB_FILL_NONE);
}

extern "C" void kernel_launch(void* const* d_in, const int* in_sizes, int n_in,
                              void* d_out, int out_size)
{
    const float* G   = (const float*)d_in[0];
    const float* S   = (const float*)d_in[1];
    const float* C   = (const float*)d_in[2];
    const float* Y   = (const float*)d_in[3];
    const float* L   = (const float*)d_in[4];
    const float* psi = (const float*)d_in[5];
    const float* gS  = (const float*)d_in[6];
    const float* gC  = (const float*)d_in[7];
    const float* gG  = (const float*)d_in[8];
    const float* gGS = (const float*)d_in[9];
    const float* gGC = (const float*)d_in[10];
    const float* gLw = (const float*)d_in[11];
    const float* lsz = (const float*)d_in[12];
    const float* b0  = (const float*)d_in[13];
    const float* bZ  = (const float*)d_in[14];
    const float* bS  = (const float*)d_in[15];
    const float* bG  = (const float*)d_in[16];
    const float* bGS = (const float*)d_in[17];
    const float* bLw = (const float*)d_in[18];

    const int N = in_sizes[0];
    const size_t NT = (size_t)N * T_STEPS;

    float* out = (float*)d_out;
    float* Zf  = out;
    float* Zv  = out + NT;
    float* llp = out + 2 * NT;

    EncFn enc = get_encoder();
    CUtensorMap tmS, tmC, tmY, tmZf, tmZv;
    make_map(enc, &tmS,  S,  N);
    make_map(enc, &tmC,  C,  N);
    make_map(enc, &tmY,  Y,  N);
    make_map(enc, &tmZf, Zf, N);
    make_map(enc, &tmZv, Zv, N);

    cudaFuncSetAttribute(hmm_filter_tma,
                         cudaFuncAttributeMaxDynamicSharedMemorySize, SMEM_DYN);

    const int blocks = (N + ROWS - 1) / ROWS;
    hmm_filter_tma<<<blocks, THREADS, SMEM_DYN>>>(
        tmS, tmC, tmY, tmZf, tmZv,
        G, L,
        psi, gS, gC, gG, gGS, gGC, gLw, lsz,
        b0, bZ, bS, bG, bGS, bLw,
        llp, N);
}